// round 4
// baseline (speedup 1.0000x reference)
#include <cuda_runtime.h>
#include <cstddef>

// Problem constants
#define BT      65536      // B*T rows
#define DDIM    64
#define KCODES  1024
#define BM      64         // rows per block
#define BN      64         // codes per chunk
#define NCHUNK  (KCODES / BN)   // 16
#define ZSTRIDE 68         // padded row stride (272B, 16B aligned, conflict-free)

__device__ float g_enorm[KCODES];
__device__ float g_partial[BT / BM];   // 1024 per-block loss partials

// ---------------------------------------------------------------------------
// Kernel 0: per-code squared norms, sequential fp32 (matches reference order)
// ---------------------------------------------------------------------------
__global__ __launch_bounds__(256) void enorm_kernel(const float* __restrict__ emb) {
    int c = blockIdx.x * 256 + threadIdx.x;
    if (c < KCODES) {
        const float* e = emb + (size_t)c * DDIM;
        float s = 0.0f;
        #pragma unroll
        for (int d = 0; d < DDIM; ++d)
            s = __fadd_rn(s, __fmul_rn(e[d], e[d]));
        g_enorm[c] = s;
    }
}

// ---------------------------------------------------------------------------
// Kernel 1: main VQ — distances + argmin + gather + per-block loss partial
// ---------------------------------------------------------------------------
__global__ __launch_bounds__(256) void vq_main(const float* __restrict__ z,
                                               const float* __restrict__ emb,
                                               float* __restrict__ out_zq,
                                               float* __restrict__ out_idx) {
    __shared__ float zS[BM][ZSTRIDE];
    __shared__ float eS[BN][ZSTRIDE];
    __shared__ float zn[BM];
    __shared__ int   idx_s[BM];
    __shared__ float red[256];

    const int tid  = threadIdx.x;
    const int tx   = tid & 15;    // code group
    const int ty   = tid >> 4;    // row group
    const int row0 = blockIdx.x * BM;

    // ---- load z tile (64x64) and emb chunk 0 into registers -> smem ----
    float4 zreg[4], ereg[4];
    #pragma unroll
    for (int i = 0; i < 4; ++i) {
        int f  = tid + i * 256;       // 0..1023 float4 index
        int r  = f >> 4;              // 0..63
        int d0 = (f & 15) << 2;       // 0..60
        zreg[i] = *(const float4*)(z   + (size_t)(row0 + r) * DDIM + d0);
        ereg[i] = *(const float4*)(emb + (size_t)r          * DDIM + d0);
    }
    #pragma unroll
    for (int i = 0; i < 4; ++i) {
        int f = tid + i * 256; int r = f >> 4; int d0 = (f & 15) << 2;
        *(float4*)&zS[r][d0] = zreg[i];
    }
    __syncthreads();

    // per-row ||z||^2, sequential fp32 (mul-then-add like jnp.sum(z*z))
    if (tid < BM) {
        float s = 0.0f;
        #pragma unroll
        for (int d = 0; d < DDIM; ++d) {
            float v = zS[tid][d];
            s = __fadd_rn(s, __fmul_rn(v, v));
        }
        zn[tid] = s;
    }
    #pragma unroll
    for (int i = 0; i < 4; ++i) {
        int f = tid + i * 256; int r = f >> 4; int d0 = (f & 15) << 2;
        *(float4*)&eS[r][d0] = ereg[i];
    }
    __syncthreads();

    float znr[4];
    #pragma unroll
    for (int ii = 0; ii < 4; ++ii) znr[ii] = zn[ty + 16 * ii];

    float mind[4];
    int   mini[4];
    #pragma unroll
    for (int ii = 0; ii < 4; ++ii) { mind[ii] = 3.402823466e38f; mini[ii] = 0; }

    // ---- main loop over 16 code chunks ----
    for (int c = 0; c < NCHUNK; ++c) {
        const int c0 = c * BN;

        // prefetch next chunk into registers (latency hidden by compute)
        if (c + 1 < NCHUNK) {
            #pragma unroll
            for (int i = 0; i < 4; ++i) {
                int f = tid + i * 256; int r = f >> 4; int d0 = (f & 15) << 2;
                ereg[i] = *(const float4*)(emb + (size_t)(c0 + BN + r) * DDIM + d0);
            }
        }

        float acc[4][4];
        #pragma unroll
        for (int ii = 0; ii < 4; ++ii)
            #pragma unroll
            for (int jj = 0; jj < 4; ++jj) acc[ii][jj] = 0.0f;

        // sequential-FMA dot over d (ascending) — one accumulator per pair
        #pragma unroll
        for (int k0 = 0; k0 < DDIM; k0 += 4) {
            float4 za[4], eb[4];
            #pragma unroll
            for (int ii = 0; ii < 4; ++ii)
                za[ii] = *(const float4*)&zS[ty + 16 * ii][k0];
            #pragma unroll
            for (int jj = 0; jj < 4; ++jj)
                eb[jj] = *(const float4*)&eS[tx + 16 * jj][k0];
            #pragma unroll
            for (int ii = 0; ii < 4; ++ii)
                #pragma unroll
                for (int jj = 0; jj < 4; ++jj) {
                    float a = acc[ii][jj];
                    a = __fmaf_rn(za[ii].x, eb[jj].x, a);
                    a = __fmaf_rn(za[ii].y, eb[jj].y, a);
                    a = __fmaf_rn(za[ii].z, eb[jj].z, a);
                    a = __fmaf_rn(za[ii].w, eb[jj].w, a);
                    acc[ii][jj] = a;
                }
        }

        // dist = (||z||^2 + ||e||^2) - 2*dot, replicating reference rounding.
        // jj ascending => codes ascending => strict '<' keeps first index.
        #pragma unroll
        for (int jj = 0; jj < 4; ++jj) {
            int   code = c0 + tx + 16 * jj;
            float en   = __ldg(&g_enorm[code]);
            #pragma unroll
            for (int ii = 0; ii < 4; ++ii) {
                float t    = __fadd_rn(znr[ii], en);
                float dist = __fadd_rn(t, -2.0f * acc[ii][jj]);   // -2*acc exact
                if (dist < mind[ii]) { mind[ii] = dist; mini[ii] = code; }
            }
        }

        __syncthreads();
        if (c + 1 < NCHUNK) {
            #pragma unroll
            for (int i = 0; i < 4; ++i) {
                int f = tid + i * 256; int r = f >> 4; int d0 = (f & 15) << 2;
                *(float4*)&eS[r][d0] = ereg[i];
            }
            __syncthreads();
        }
    }

    // ---- argmin reduce across the 16 code-threads (lane groups of 16) ----
    #pragma unroll
    for (int ii = 0; ii < 4; ++ii) {
        float d  = mind[ii];
        int   ix = mini[ii];
        #pragma unroll
        for (int m = 8; m >= 1; m >>= 1) {
            float od = __shfl_xor_sync(0xffffffffu, d,  m);
            int   oi = __shfl_xor_sync(0xffffffffu, ix, m);
            if (od < d || (od == d && oi < ix)) { d = od; ix = oi; }
        }
        if (tx == 0) idx_s[ty + 16 * ii] = ix;
    }
    __syncthreads();

    // ---- gather z_q = emb[idx], write idx, accumulate (z_q - z)^2 ----
    {
        int   r    = tid >> 2;     // row 0..63, 4 threads per row
        int   q    = tid & 3;      // quarter of headdim
        int   ix   = idx_s[r];
        int   grow = row0 + r;
        float psum = 0.0f;
        #pragma unroll
        for (int s4 = 0; s4 < 4; ++s4) {
            int d0 = q * 16 + s4 * 4;
            float4 e4 = *(const float4*)(emb + (size_t)ix * DDIM + d0);
            float4 z4 = *(const float4*)&zS[r][d0];
            float dx = __fadd_rn(e4.x, -z4.x);
            float dy = __fadd_rn(e4.y, -z4.y);
            float dz = __fadd_rn(e4.z, -z4.z);
            float dw = __fadd_rn(e4.w, -z4.w);
            psum = __fmaf_rn(dx, dx, psum);
            psum = __fmaf_rn(dy, dy, psum);
            psum = __fmaf_rn(dz, dz, psum);
            psum = __fmaf_rn(dw, dw, psum);
            *(float4*)(out_zq + (size_t)grow * DDIM + d0) = e4;
        }
        if (q == 0) out_idx[grow] = (float)ix;
        red[tid] = psum;
    }
    __syncthreads();
    #pragma unroll
    for (int s = 128; s > 0; s >>= 1) {
        if (tid < s) red[tid] = __fadd_rn(red[tid], red[tid + s]);
        __syncthreads();
    }
    if (tid == 0) g_partial[blockIdx.x] = red[0];
}

// ---------------------------------------------------------------------------
// Kernel 2: deterministic loss reduction
// loss = sum_b [ BETA*mean + mean ] = 1.25 * (global sq sum) / (T*D)
// ---------------------------------------------------------------------------
__global__ __launch_bounds__(256) void loss_kernel(float* __restrict__ out_loss) {
    __shared__ float s[256];
    int tid = threadIdx.x;
    float v = g_partial[tid];
    v = __fadd_rn(v, g_partial[tid + 256]);
    v = __fadd_rn(v, g_partial[tid + 512]);
    v = __fadd_rn(v, g_partial[tid + 768]);
    s[tid] = v;
    __syncthreads();
    #pragma unroll
    for (int t = 128; t > 0; t >>= 1) {
        if (tid < t) s[tid] = __fadd_rn(s[tid], s[tid + t]);
        __syncthreads();
    }
    if (tid == 0)
        out_loss[0] = 1.25f * (s[0] * (1.0f / 262144.0f));  // 1/(4096*64)
}

// ---------------------------------------------------------------------------
extern "C" void kernel_launch(void* const* d_in, const int* in_sizes, int n_in,
                              void* d_out, int out_size) {
    const float* a0 = (const float*)d_in[0];
    const float* a1 = (const float*)d_in[1];
    const float* z;
    const float* emb;
    // metadata order should be (z, emb); guard by size just in case
    if (in_sizes[0] == BT * DDIM) { z = a0; emb = a1; }
    else                          { z = a1; emb = a0; }

    float* out      = (float*)d_out;
    float* out_zq   = out;                                  // 4,194,304
    float* out_loss = out + (size_t)BT * DDIM;              // 1
    float* out_idx  = out + (size_t)BT * DDIM + 1;          // 65,536

    enorm_kernel<<<(KCODES + 255) / 256, 256>>>(emb);
    vq_main<<<BT / BM, 256>>>(z, emb, out_zq, out_idx);
    loss_kernel<<<1, 256>>>(out_loss);
}